// round 2
// baseline (speedup 1.0000x reference)
#include <cuda_runtime.h>
#include <cstddef>

#define BB 8
#define NN 8192
#define MM 1024
#define KK 32
#define CIN 67
#define NH1 64
#define NH2 64
#define NH3 128

// scratch: ball-query neighbor indices (B*M*K)
__device__ int g_gidx[BB * MM * KK];

// ---------------------------------------------------------------------------
// Kernel 1: Farthest Point Sampling. One block per batch, 1024 threads,
// 8 points per thread held in registers. One __syncthreads per step.
// Distance math forced to mul+add (no FMA) to match the reference bit-for-bit.
// Tie-break: lowest index wins (jnp.argmax first-max semantics).
// Writes new_xyz directly into d_out region 0.
// ---------------------------------------------------------------------------
__global__ __launch_bounds__(1024) void fps_kernel(const float* __restrict__ xyz,
                                                   float* __restrict__ out_xyz) {
    const int b = blockIdx.x;
    const int t = threadIdx.x;
    const int lane = t & 31;
    const int warp = t >> 5;
    const float* X = xyz + (size_t)b * NN * 3;

    float px[8], py[8], pz[8], dd[8];
#pragma unroll
    for (int i = 0; i < 8; i++) {
        int p = t + (i << 10);
        px[i] = X[p * 3 + 0];
        py[i] = X[p * 3 + 1];
        pz[i] = X[p * 3 + 2];
        dd[i] = 1e10f;
    }

    __shared__ unsigned long long wkey[2][32];

    float lx = X[0], ly = X[1], lz = X[2];  // first centroid = point 0
    if (t == 0) {
        float* o = out_xyz + (size_t)b * MM * 3;
        o[0] = lx; o[1] = ly; o[2] = lz;
    }

    for (int s = 1; s < MM; s++) {
        float bestd = -1.0f;
        int besti = 0;
#pragma unroll
        for (int i = 0; i < 8; i++) {
            float dx = __fadd_rn(px[i], -lx);
            float dy = __fadd_rn(py[i], -ly);
            float dz = __fadd_rn(pz[i], -lz);
            float d = __fadd_rn(__fadd_rn(__fmul_rn(dx, dx), __fmul_rn(dy, dy)),
                                __fmul_rn(dz, dz));
            float nd = fminf(dd[i], d);
            dd[i] = nd;
            // strict > keeps the earliest (lowest) index within this thread
            if (nd > bestd) { bestd = nd; besti = t + (i << 10); }
        }
        // pack: high 32 = dist bits (nonneg float => uint order), low 32 = N-1-idx
        unsigned long long key =
            ((unsigned long long)__float_as_uint(bestd) << 32) |
            (unsigned)(NN - 1 - besti);
#pragma unroll
        for (int off = 16; off > 0; off >>= 1) {
            unsigned long long o = __shfl_xor_sync(0xffffffffu, key, off);
            if (o > key) key = o;
        }
        if (lane == 0) wkey[s & 1][warp] = key;
        __syncthreads();
        unsigned long long k2 = wkey[s & 1][lane];
#pragma unroll
        for (int off = 16; off > 0; off >>= 1) {
            unsigned long long o = __shfl_xor_sync(0xffffffffu, k2, off);
            if (o > k2) k2 = o;
        }
        int sel = (NN - 1) - (int)(unsigned)(k2 & 0xffffffffULL);
        // every thread fetches the selected point (broadcast LDG, L1-resident)
        lx = __ldg(X + sel * 3 + 0);
        ly = __ldg(X + sel * 3 + 1);
        lz = __ldg(X + sel * 3 + 2);
        if (t == 0) {
            float* o = out_xyz + ((size_t)b * MM + s) * 3;
            o[0] = lx; o[1] = ly; o[2] = lz;
        }
    }
}

// ---------------------------------------------------------------------------
// Kernel 2: ball query — one warp per query point, first-32 hits in index
// order, padded with the first hit (reference semantics).
// ---------------------------------------------------------------------------
__global__ __launch_bounds__(256) void ballq_kernel(const float* __restrict__ xyz,
                                                    const float* __restrict__ new_xyz) {
    const int w = (blockIdx.x * blockDim.x + threadIdx.x) >> 5;
    const int lane = threadIdx.x & 31;
    if (w >= BB * MM) return;
    const int b = w >> 10;
    const float* X = xyz + (size_t)b * NN * 3;
    const float cx = new_xyz[w * 3 + 0];
    const float cy = new_xyz[w * 3 + 1];
    const float cz = new_xyz[w * 3 + 2];
    const float R2 = (float)(0.4 * 0.4);  // fl(0.16000000000000003) — NOT 0.4f*0.4f

    int cnt = 0;
    int first = -1;
    int* out = g_gidx + (size_t)w * KK;

    for (int base = 0; base < NN && cnt < KK; base += 32) {
        int i = base + lane;
        float x = X[i * 3 + 0], y = X[i * 3 + 1], z = X[i * 3 + 2];
        float dx = __fadd_rn(x, -cx);
        float dy = __fadd_rn(y, -cy);
        float dz = __fadd_rn(z, -cz);
        float d2 = __fadd_rn(__fadd_rn(__fmul_rn(dx, dx), __fmul_rn(dy, dy)),
                             __fmul_rn(dz, dz));
        bool hit = d2 < R2;
        unsigned msk = __ballot_sync(0xffffffffu, hit);
        if (msk) {
            if (first < 0) first = base + __ffs(msk) - 1;
            int pos = cnt + __popc(msk & ((1u << lane) - 1u));
            if (hit && pos < KK) out[pos] = i;
            cnt += __popc(msk);
        }
    }
    if (cnt < KK) {
        for (int s2 = cnt + lane; s2 < KK; s2 += 32) out[s2] = first;
    }
}

// ---------------------------------------------------------------------------
// Kernel 3: fused gather + 3-layer MLP + max-pool over K.
// 256 threads = 2 groups of 128; each 128-thread half handles one (b,m) group
// of 32 neighbors. Weights transposed to [c][o] in smem (shared by both
// halves). Register tiles: 4k x 4o (layers 1/2), 4k x 8o (layer 3).
// Smem: 101120 B -> 2 blocks/SM.
// ---------------------------------------------------------------------------
__global__ __launch_bounds__(256) void mlp_kernel(
    const float* __restrict__ xyz, const float* __restrict__ feat,
    const float* __restrict__ w1, const float* __restrict__ b1,
    const float* __restrict__ w2, const float* __restrict__ b2,
    const float* __restrict__ w3, const float* __restrict__ b3,
    const float* __restrict__ new_xyz, float* __restrict__ out_feat) {
    extern __shared__ float sm[];
    float* w1t = sm;            // 67*64 = 4288
    float* w2t = sm + 4288;     // 64*64 = 4096
    float* w3t = sm + 8384;     // 64*128 = 8192
    float* b1s = sm + 16576;    // 64
    float* b2s = sm + 16640;    // 64
    float* b3s = sm + 16704;    // 128
    const int tid = threadIdx.x;
    const int half = tid >> 7;
    const int t = tid & 127;
    float* xs = sm + 16832 + half * 2144;   // 32x67 input, reused as h2 (stride 65)
    float* h1s = sm + 21120 + half * 2080;  // 32x65

    // cooperative transposed weight load
    for (int e = tid; e < NH1 * CIN; e += 256) {
        int o = e / CIN, c = e - o * CIN;
        w1t[c * 64 + o] = w1[e];
    }
    for (int e = tid; e < NH2 * NH1; e += 256) {
        int o = e >> 6, c = e & 63;
        w2t[c * 64 + o] = w2[e];
    }
    for (int e = tid; e < NH3 * NH2; e += 256) {
        int o = e >> 6, c = e & 63;
        w3t[c * 128 + o] = w3[e];
    }
    if (tid < 64) b1s[tid] = b1[tid];
    else if (tid < 128) b2s[tid - 64] = b2[tid - 64];
    else b3s[tid - 128] = b3[tid - 128];

    const int g = blockIdx.x * 2 + half;
    const int b = g >> 10;
    const int m = g & 1023;
    const float cx = new_xyz[g * 3 + 0];
    const float cy = new_xyz[g * 3 + 1];
    const float cz = new_xyz[g * 3 + 2];
    const int* gix = g_gidx + (size_t)g * KK;
    const float* Xb = xyz + (size_t)b * NN * 3;
    const float* Fb = feat + (size_t)b * NN * 64;

    // gather input: x[k][c], c<3 = relative xyz, c>=3 = features
    for (int e = t; e < KK * CIN; e += 128) {
        int k = e / CIN, c = e - k * CIN;
        int gi = gix[k];
        float v;
        if (c < 3) {
            float ctr = (c == 0) ? cx : ((c == 1) ? cy : cz);
            v = Xb[gi * 3 + c] - ctr;
        } else {
            v = Fb[(size_t)gi * 64 + (c - 3)];
        }
        xs[k * CIN + c] = v;
    }
    __syncthreads();

    const int kt = t & 7;     // 8 k-tiles of 4
    const int ot = t >> 3;    // 16 o-tiles

    // ---- layer 1: 67 -> 64 ----
    float a1[4][4];
#pragma unroll
    for (int i = 0; i < 4; i++)
#pragma unroll
        for (int j = 0; j < 4; j++) a1[i][j] = b1s[ot * 4 + j];
    for (int c = 0; c < CIN; c++) {
        float xv[4], wv[4];
#pragma unroll
        for (int i = 0; i < 4; i++) xv[i] = xs[(kt * 4 + i) * CIN + c];
#pragma unroll
        for (int j = 0; j < 4; j++) wv[j] = w1t[c * 64 + ot * 4 + j];
#pragma unroll
        for (int i = 0; i < 4; i++)
#pragma unroll
            for (int j = 0; j < 4; j++) a1[i][j] = fmaf(xv[i], wv[j], a1[i][j]);
    }
#pragma unroll
    for (int i = 0; i < 4; i++)
#pragma unroll
        for (int j = 0; j < 4; j++)
            h1s[(kt * 4 + i) * 65 + ot * 4 + j] = fmaxf(a1[i][j], 0.0f);
    __syncthreads();

    // ---- layer 2: 64 -> 64 ----
    float a2[4][4];
#pragma unroll
    for (int i = 0; i < 4; i++)
#pragma unroll
        for (int j = 0; j < 4; j++) a2[i][j] = b2s[ot * 4 + j];
    for (int c = 0; c < NH1; c++) {
        float xv[4], wv[4];
#pragma unroll
        for (int i = 0; i < 4; i++) xv[i] = h1s[(kt * 4 + i) * 65 + c];
#pragma unroll
        for (int j = 0; j < 4; j++) wv[j] = w2t[c * 64 + ot * 4 + j];
#pragma unroll
        for (int i = 0; i < 4; i++)
#pragma unroll
            for (int j = 0; j < 4; j++) a2[i][j] = fmaf(xv[i], wv[j], a2[i][j]);
    }
    // h2 overwrites xs (x dead after layer 1) — stride 65
#pragma unroll
    for (int i = 0; i < 4; i++)
#pragma unroll
        for (int j = 0; j < 4; j++)
            xs[(kt * 4 + i) * 65 + ot * 4 + j] = fmaxf(a2[i][j], 0.0f);
    __syncthreads();

    // ---- layer 3: 64 -> 128, then max over k ----
    float a3[4][8];
#pragma unroll
    for (int i = 0; i < 4; i++)
#pragma unroll
        for (int j = 0; j < 8; j++) a3[i][j] = b3s[ot * 8 + j];
    for (int c = 0; c < NH2; c++) {
        float xv[4], wv[8];
#pragma unroll
        for (int i = 0; i < 4; i++) xv[i] = xs[(kt * 4 + i) * 65 + c];
#pragma unroll
        for (int j = 0; j < 8; j++) wv[j] = w3t[c * 128 + ot * 8 + j];
#pragma unroll
        for (int i = 0; i < 4; i++)
#pragma unroll
            for (int j = 0; j < 8; j++) a3[i][j] = fmaf(xv[i], wv[j], a3[i][j]);
    }
    float v[8];
#pragma unroll
    for (int j = 0; j < 8; j++) {
        float mx = fmaxf(fmaxf(a3[0][j], a3[1][j]), fmaxf(a3[2][j], a3[3][j]));
        v[j] = fmaxf(mx, 0.0f);  // relu commutes with max
    }
    // reduce across the 8 kt lanes (lane bits 0..2)
#pragma unroll
    for (int d = 1; d < 8; d <<= 1)
#pragma unroll
        for (int j = 0; j < 8; j++)
            v[j] = fmaxf(v[j], __shfl_xor_sync(0xffffffffu, v[j], d));
    if (kt == 0) {
#pragma unroll
        for (int j = 0; j < 8; j++)
            out_feat[((size_t)b * NH3 + ot * 8 + j) * MM + m] = v[j];
    }
}

// ---------------------------------------------------------------------------
extern "C" void kernel_launch(void* const* d_in, const int* in_sizes, int n_in,
                              void* d_out, int out_size) {
    const float* xyz = (const float*)d_in[0];
    const float* feat = (const float*)d_in[1];
    const float* w1 = (const float*)d_in[2];
    const float* b1 = (const float*)d_in[3];
    const float* w2 = (const float*)d_in[4];
    const float* b2 = (const float*)d_in[5];
    const float* w3 = (const float*)d_in[6];
    const float* b3 = (const float*)d_in[7];

    float* out = (float*)d_out;
    float* out_xyz = out;                 // (8,1024,3)
    float* out_feat = out + BB * MM * 3;  // (8,128,1024)

    fps_kernel<<<BB, 1024>>>(xyz, out_xyz);
    ballq_kernel<<<(BB * MM * 32) / 256, 256>>>(xyz, out_xyz);

    const int smem_bytes = 25280 * 4;  // 101120 B
    cudaFuncSetAttribute(mlp_kernel, cudaFuncAttributeMaxDynamicSharedMemorySize,
                         smem_bytes);
    mlp_kernel<<<BB * MM / 2, 256, smem_bytes>>>(xyz, feat, w1, b1, w2, b2, w3, b3,
                                                 out_xyz, out_feat);
}

// round 3
// speedup vs baseline: 1.3647x; 1.3647x over previous
#include <cuda_runtime.h>
#include <cstddef>

#define BB 8
#define NN 8192
#define MM 1024
#define KK 32
#define CIN 67
#define NH1 64
#define NH2 64
#define NH3 128

typedef unsigned long long ull;

// packed f32x2 helpers (Blackwell sm_103a). Per-lane IEEE .rn — bit-identical
// to the corresponding scalar ops.
__device__ __forceinline__ ull f2pack(float lo, float hi) {
    ull r; asm("mov.b64 %0,{%1,%2};" : "=l"(r) : "f"(lo), "f"(hi)); return r;
}
__device__ __forceinline__ void f2unpack(float& lo, float& hi, ull v) {
    asm("mov.b64 {%0,%1},%2;" : "=f"(lo), "=f"(hi) : "l"(v));
}
__device__ __forceinline__ ull add2(ull a, ull b) {
    ull r; asm("add.rn.f32x2 %0,%1,%2;" : "=l"(r) : "l"(a), "l"(b)); return r;
}
__device__ __forceinline__ ull mul2(ull a, ull b) {
    ull r; asm("mul.rn.f32x2 %0,%1,%2;" : "=l"(r) : "l"(a), "l"(b)); return r;
}
__device__ __forceinline__ ull fma2(ull a, ull b, ull c) {
    ull r; asm("fma.rn.f32x2 %0,%1,%2,%3;" : "=l"(r) : "l"(a), "l"(b), "l"(c)); return r;
}

// scratch: ball-query neighbor indices (B*M*K)
__device__ int g_gidx[BB * MM * KK];

// ---------------------------------------------------------------------------
// Kernel 1: Farthest Point Sampling. One block per batch, 1024 threads,
// 8 points/thread in registers, packed f32x2 distance math (bit-exact vs
// scalar mul/add), redux-based argmax with lowest-index tie-break.
// ---------------------------------------------------------------------------
__global__ __launch_bounds__(1024) void fps_kernel(const float* __restrict__ xyz,
                                                   float* __restrict__ out_xyz) {
    const int b = blockIdx.x;
    const int t = threadIdx.x;
    const int lane = t & 31;
    const int warp = t >> 5;
    const float* X = xyz + (size_t)b * NN * 3;

    // 4 pairs: pair p holds points (t + 2p*1024, t + (2p+1)*1024)
    ull px2[4], py2[4], pz2[4];
    float dd[8];
#pragma unroll
    for (int p = 0; p < 4; p++) {
        int i0 = t + (p << 11);
        int i1 = i0 + 1024;
        px2[p] = f2pack(X[i0 * 3 + 0], X[i1 * 3 + 0]);
        py2[p] = f2pack(X[i0 * 3 + 1], X[i1 * 3 + 1]);
        pz2[p] = f2pack(X[i0 * 3 + 2], X[i1 * 3 + 2]);
        dd[2 * p] = 1e10f;
        dd[2 * p + 1] = 1e10f;
    }

    __shared__ unsigned sdist[2][32];
    __shared__ unsigned sidx[2][32];

    float lx = X[0], ly = X[1], lz = X[2];  // first centroid = point 0
    if (t == 0) {
        float* o = out_xyz + (size_t)b * MM * 3;
        o[0] = lx; o[1] = ly; o[2] = lz;
    }

    for (int s = 1; s < MM; s++) {
        const ull nlx = f2pack(-lx, -lx);
        const ull nly = f2pack(-ly, -ly);
        const ull nlz = f2pack(-lz, -lz);
        float bestd = -1.0f;
        int besti = 0;
#pragma unroll
        for (int p = 0; p < 4; p++) {
            ull dx = add2(px2[p], nlx);     // x + (-cx) == x - cx exactly
            ull dy = add2(py2[p], nly);
            ull dz = add2(pz2[p], nlz);
            ull xx = mul2(dx, dx);
            ull yy = mul2(dy, dy);
            ull zz = mul2(dz, dz);
            ull ss = add2(add2(xx, yy), zz);  // ((dx²+dy²)+dz²) per lane
            float s0, s1;
            f2unpack(s0, s1, ss);
            float n0 = fminf(dd[2 * p], s0);
            dd[2 * p] = n0;
            if (n0 > bestd) { bestd = n0; besti = t + (p << 11); }
            float n1 = fminf(dd[2 * p + 1], s1);
            dd[2 * p + 1] = n1;
            if (n1 > bestd) { bestd = n1; besti = t + (p << 11) + 1024; }
        }
        // warp argmax: dists >= 0, so uint order on float bits == float order.
        unsigned bd = __float_as_uint(bestd);
        unsigned mx = __reduce_max_sync(0xffffffffu, bd);
        unsigned cand = (bd == mx) ? (unsigned)besti : 0xffffffffu;
        unsigned wsel = __reduce_min_sync(0xffffffffu, cand);
        if (lane == 0) {
            sdist[s & 1][warp] = mx;
            sidx[s & 1][warp] = wsel;
        }
        __syncthreads();
        unsigned d2 = sdist[s & 1][lane];
        unsigned i2 = sidx[s & 1][lane];
        unsigned mx2 = __reduce_max_sync(0xffffffffu, d2);
        unsigned cand2 = (d2 == mx2) ? i2 : 0xffffffffu;
        int sel = (int)__reduce_min_sync(0xffffffffu, cand2);
        // broadcast LDG of the selected point (L1-resident after first pass)
        lx = __ldg(X + sel * 3 + 0);
        ly = __ldg(X + sel * 3 + 1);
        lz = __ldg(X + sel * 3 + 2);
        if (t == 0) {
            float* o = out_xyz + ((size_t)b * MM + s) * 3;
            o[0] = lx; o[1] = ly; o[2] = lz;
        }
    }
}

// ---------------------------------------------------------------------------
// Kernel 2: ball query — one warp per query point, first-32 hits in index
// order, padded with the first hit (reference semantics).
// ---------------------------------------------------------------------------
__global__ __launch_bounds__(256) void ballq_kernel(const float* __restrict__ xyz,
                                                    const float* __restrict__ new_xyz) {
    const int w = (blockIdx.x * blockDim.x + threadIdx.x) >> 5;
    const int lane = threadIdx.x & 31;
    if (w >= BB * MM) return;
    const int b = w >> 10;
    const float* X = xyz + (size_t)b * NN * 3;
    const float cx = new_xyz[w * 3 + 0];
    const float cy = new_xyz[w * 3 + 1];
    const float cz = new_xyz[w * 3 + 2];
    const float R2 = (float)(0.4 * 0.4);  // fl(0.16000000000000003) — NOT 0.4f*0.4f

    int cnt = 0;
    int first = -1;
    int* out = g_gidx + (size_t)w * KK;

    for (int base = 0; base < NN && cnt < KK; base += 32) {
        int i = base + lane;
        float x = X[i * 3 + 0], y = X[i * 3 + 1], z = X[i * 3 + 2];
        float dx = __fadd_rn(x, -cx);
        float dy = __fadd_rn(y, -cy);
        float dz = __fadd_rn(z, -cz);
        float d2 = __fadd_rn(__fadd_rn(__fmul_rn(dx, dx), __fmul_rn(dy, dy)),
                             __fmul_rn(dz, dz));
        bool hit = d2 < R2;
        unsigned msk = __ballot_sync(0xffffffffu, hit);
        if (msk) {
            if (first < 0) first = base + __ffs(msk) - 1;
            int pos = cnt + __popc(msk & ((1u << lane) - 1u));
            if (hit && pos < KK) out[pos] = i;
            cnt += __popc(msk);
        }
    }
    if (cnt < KK) {
        for (int s2 = cnt + lane; s2 < KK; s2 += 32) out[s2] = first;
    }
}

// ---------------------------------------------------------------------------
// Kernel 3: fused gather + 3-layer MLP + max-pool over K, with packed
// fma.rn.f32x2 accumulators over the output dimension (weight pairs adjacent
// in the transposed smem layout -> LDS.64).
// 256 threads = 2 groups of 128; each half handles one (b,m) group.
// ---------------------------------------------------------------------------
__global__ __launch_bounds__(256) void mlp_kernel(
    const float* __restrict__ xyz, const float* __restrict__ feat,
    const float* __restrict__ w1, const float* __restrict__ b1,
    const float* __restrict__ w2, const float* __restrict__ b2,
    const float* __restrict__ w3, const float* __restrict__ b3,
    const float* __restrict__ new_xyz, float* __restrict__ out_feat) {
    extern __shared__ float sm[];
    float* w1t = sm;            // 67*64 = 4288
    float* w2t = sm + 4288;     // 64*64 = 4096
    float* w3t = sm + 8384;     // 64*128 = 8192
    float* b1s = sm + 16576;    // 64
    float* b2s = sm + 16640;    // 64
    float* b3s = sm + 16704;    // 128
    const int tid = threadIdx.x;
    const int half = tid >> 7;
    const int t = tid & 127;
    float* xs = sm + 16832 + half * 2144;   // 32x67 input, reused as h2 (stride 65)
    float* h1s = sm + 21120 + half * 2080;  // 32x65

    // cooperative transposed weight load
    for (int e = tid; e < NH1 * CIN; e += 256) {
        int o = e / CIN, c = e - o * CIN;
        w1t[c * 64 + o] = w1[e];
    }
    for (int e = tid; e < NH2 * NH1; e += 256) {
        int o = e >> 6, c = e & 63;
        w2t[c * 64 + o] = w2[e];
    }
    for (int e = tid; e < NH3 * NH2; e += 256) {
        int o = e >> 6, c = e & 63;
        w3t[c * 128 + o] = w3[e];
    }
    if (tid < 64) b1s[tid] = b1[tid];
    else if (tid < 128) b2s[tid - 64] = b2[tid - 64];
    else b3s[tid - 128] = b3[tid - 128];

    const int g = blockIdx.x * 2 + half;
    const int b = g >> 10;
    const int m = g & 1023;
    const float cx = new_xyz[g * 3 + 0];
    const float cy = new_xyz[g * 3 + 1];
    const float cz = new_xyz[g * 3 + 2];
    const int* gix = g_gidx + (size_t)g * KK;
    const float* Xb = xyz + (size_t)b * NN * 3;
    const float* Fb = feat + (size_t)b * NN * 64;

    // gather input: x[k][c], c<3 = relative xyz, c>=3 = features
    for (int e = t; e < KK * CIN; e += 128) {
        int k = e / CIN, c = e - k * CIN;
        int gi = gix[k];
        float v;
        if (c < 3) {
            float ctr = (c == 0) ? cx : ((c == 1) ? cy : cz);
            v = Xb[gi * 3 + c] - ctr;
        } else {
            v = Fb[(size_t)gi * 64 + (c - 3)];
        }
        xs[k * CIN + c] = v;
    }
    __syncthreads();

    const int kt = t & 7;     // 8 k-tiles of 4
    const int ot = t >> 3;    // 16 o-tiles

    // ---- layer 1: 67 -> 64 (4k x 4o, o packed as 2x f32x2) ----
    ull a1[4][2];
    {
        ull bv0 = *(const ull*)&b1s[ot * 4 + 0];
        ull bv1 = *(const ull*)&b1s[ot * 4 + 2];
#pragma unroll
        for (int i = 0; i < 4; i++) { a1[i][0] = bv0; a1[i][1] = bv1; }
    }
    for (int c = 0; c < CIN; c++) {
        ull wv0 = *(const ull*)&w1t[c * 64 + ot * 4 + 0];
        ull wv1 = *(const ull*)&w1t[c * 64 + ot * 4 + 2];
#pragma unroll
        for (int i = 0; i < 4; i++) {
            float xv = xs[(kt * 4 + i) * CIN + c];
            ull xp = f2pack(xv, xv);
            a1[i][0] = fma2(xp, wv0, a1[i][0]);
            a1[i][1] = fma2(xp, wv1, a1[i][1]);
        }
    }
#pragma unroll
    for (int i = 0; i < 4; i++)
#pragma unroll
        for (int j = 0; j < 2; j++) {
            float lo, hi;
            f2unpack(lo, hi, a1[i][j]);
            h1s[(kt * 4 + i) * 65 + ot * 4 + 2 * j + 0] = fmaxf(lo, 0.0f);
            h1s[(kt * 4 + i) * 65 + ot * 4 + 2 * j + 1] = fmaxf(hi, 0.0f);
        }
    __syncthreads();

    // ---- layer 2: 64 -> 64 ----
    ull a2[4][2];
    {
        ull bv0 = *(const ull*)&b2s[ot * 4 + 0];
        ull bv1 = *(const ull*)&b2s[ot * 4 + 2];
#pragma unroll
        for (int i = 0; i < 4; i++) { a2[i][0] = bv0; a2[i][1] = bv1; }
    }
    for (int c = 0; c < NH1; c++) {
        ull wv0 = *(const ull*)&w2t[c * 64 + ot * 4 + 0];
        ull wv1 = *(const ull*)&w2t[c * 64 + ot * 4 + 2];
#pragma unroll
        for (int i = 0; i < 4; i++) {
            float xv = h1s[(kt * 4 + i) * 65 + c];
            ull xp = f2pack(xv, xv);
            a2[i][0] = fma2(xp, wv0, a2[i][0]);
            a2[i][1] = fma2(xp, wv1, a2[i][1]);
        }
    }
    // h2 overwrites xs (x dead after layer 1) — stride 65
#pragma unroll
    for (int i = 0; i < 4; i++)
#pragma unroll
        for (int j = 0; j < 2; j++) {
            float lo, hi;
            f2unpack(lo, hi, a2[i][j]);
            xs[(kt * 4 + i) * 65 + ot * 4 + 2 * j + 0] = fmaxf(lo, 0.0f);
            xs[(kt * 4 + i) * 65 + ot * 4 + 2 * j + 1] = fmaxf(hi, 0.0f);
        }
    __syncthreads();

    // ---- layer 3: 64 -> 128 (4k x 8o packed as 4x f32x2), then max over k ----
    ull a3[4][4];
    {
#pragma unroll
        for (int j = 0; j < 4; j++) {
            ull bv = *(const ull*)&b3s[ot * 8 + 2 * j];
#pragma unroll
            for (int i = 0; i < 4; i++) a3[i][j] = bv;
        }
    }
    for (int c = 0; c < NH2; c++) {
        ull wv[4];
#pragma unroll
        for (int j = 0; j < 4; j++) wv[j] = *(const ull*)&w3t[c * 128 + ot * 8 + 2 * j];
#pragma unroll
        for (int i = 0; i < 4; i++) {
            float xv = xs[(kt * 4 + i) * 65 + c];
            ull xp = f2pack(xv, xv);
#pragma unroll
            for (int j = 0; j < 4; j++) a3[i][j] = fma2(xp, wv[j], a3[i][j]);
        }
    }
    float v[8];
#pragma unroll
    for (int j = 0; j < 4; j++) {
        float l0, h0, l1, h1, l2, h2, l3, h3;
        f2unpack(l0, h0, a3[0][j]);
        f2unpack(l1, h1, a3[1][j]);
        f2unpack(l2, h2, a3[2][j]);
        f2unpack(l3, h3, a3[3][j]);
        v[2 * j + 0] = fmaxf(fmaxf(fmaxf(l0, l1), fmaxf(l2, l3)), 0.0f);
        v[2 * j + 1] = fmaxf(fmaxf(fmaxf(h0, h1), fmaxf(h2, h3)), 0.0f);
    }
    // reduce across the 8 kt lanes (lane bits 0..2)
#pragma unroll
    for (int d = 1; d < 8; d <<= 1)
#pragma unroll
        for (int j = 0; j < 8; j++)
            v[j] = fmaxf(v[j], __shfl_xor_sync(0xffffffffu, v[j], d));
    if (kt == 0) {
#pragma unroll
        for (int j = 0; j < 8; j++)
            out_feat[((size_t)b * NH3 + ot * 8 + j) * MM + m] = v[j];
    }
}

// ---------------------------------------------------------------------------
extern "C" void kernel_launch(void* const* d_in, const int* in_sizes, int n_in,
                              void* d_out, int out_size) {
    const float* xyz = (const float*)d_in[0];
    const float* feat = (const float*)d_in[1];
    const float* w1 = (const float*)d_in[2];
    const float* b1 = (const float*)d_in[3];
    const float* w2 = (const float*)d_in[4];
    const float* b2 = (const float*)d_in[5];
    const float* w3 = (const float*)d_in[6];
    const float* b3 = (const float*)d_in[7];

    float* out = (float*)d_out;
    float* out_xyz = out;                 // (8,1024,3)
    float* out_feat = out + BB * MM * 3;  // (8,128,1024)

    fps_kernel<<<BB, 1024>>>(xyz, out_xyz);
    ballq_kernel<<<(BB * MM * 32) / 256, 256>>>(xyz, out_xyz);

    const int smem_bytes = 25280 * 4;  // 101120 B
    cudaFuncSetAttribute(mlp_kernel, cudaFuncAttributeMaxDynamicSharedMemorySize,
                         smem_bytes);
    mlp_kernel<<<BB * MM / 2, 256, smem_bytes>>>(xyz, feat, w1, b1, w2, b2, w3, b3,
                                                 out_xyz, out_feat);
}

// round 4
// speedup vs baseline: 1.6734x; 1.2262x over previous
#include <cuda_runtime.h>
#include <cstddef>
#include <cstdint>

#define BB 8
#define NN 8192
#define MM 1024
#define KK 32
#define CIN 67
#define NH1 64
#define NH2 64
#define NH3 128

typedef unsigned long long ull;

__device__ __forceinline__ ull f2pack(float lo, float hi) {
    ull r; asm("mov.b64 %0,{%1,%2};" : "=l"(r) : "f"(lo), "f"(hi)); return r;
}
__device__ __forceinline__ void f2unpack(float& lo, float& hi, ull v) {
    asm("mov.b64 {%0,%1},%2;" : "=f"(lo), "=f"(hi) : "l"(v));
}
__device__ __forceinline__ ull add2(ull a, ull b) {
    ull r; asm("add.rn.f32x2 %0,%1,%2;" : "=l"(r) : "l"(a), "l"(b)); return r;
}
__device__ __forceinline__ ull mul2(ull a, ull b) {
    ull r; asm("mul.rn.f32x2 %0,%1,%2;" : "=l"(r) : "l"(a), "l"(b)); return r;
}
__device__ __forceinline__ ull fma2(ull a, ull b, ull c) {
    ull r; asm("fma.rn.f32x2 %0,%1,%2,%3;" : "=l"(r) : "l"(a), "l"(b), "l"(c)); return r;
}
__device__ __forceinline__ uint32_t smem_u32(const void* p) {
    uint32_t a;
    asm("{ .reg .u64 t; cvta.to.shared.u64 t, %1; cvt.u32.u64 %0, t; }" : "=r"(a) : "l"(p));
    return a;
}

#define MBAR_INIT(addr, cnt) \
    asm volatile("mbarrier.init.shared.b64 [%0], %1;" :: "r"(addr), "r"(cnt) : "memory")
#define MBAR_EXPECT_TX(addr, bytes) \
    asm volatile("mbarrier.arrive.expect_tx.shared.b64 _, [%0], %1;" :: "r"(addr), "r"(bytes) : "memory")
#define MBAR_WAIT_PARITY(addr, par) do { \
    uint32_t _m = (addr); uint32_t _p = (par); uint32_t _d; \
    asm volatile("{\n\t.reg .pred p;\n\t" \
        "mbarrier.try_wait.parity.acquire.cta.shared::cta.b64 p, [%1], %2;\n\t" \
        "selp.b32 %0, 1, 0, p;\n\t}" : "=r"(_d) : "r"(_m), "r"(_p) : "memory"); \
    if (!_d) { \
        asm volatile("{\n\t.reg .pred P1;\n\t" \
            "WL_%=:\n\t" \
            "mbarrier.try_wait.parity.acquire.cta.shared::cta.b64 P1, [%0], %1, 0x989680;\n\t" \
            "@P1 bra.uni WD_%=;\n\t" \
            "bra.uni WL_%=;\n\t" \
            "WD_%=:\n\t}" :: "r"(_m), "r"(_p) : "memory"); \
    } \
} while (0)

// scratch: ball-query neighbor indices (B*M*K)
__device__ int g_gidx[BB * MM * KK];

// ---------------------------------------------------------------------------
// Kernel 1: FPS, 2-CTA cluster per batch. Each CTA owns 4096 points
// (512 threads x 8 pts, packed f32x2 distance math, bit-exact). Per step:
// local block argmax, then key exchange with the peer CTA via
// st.async.shared::cluster + mbarrier. Key = (distbits<<32)|(8191-idx):
// max-key == argmax with lowest-index tie-break.
// ---------------------------------------------------------------------------
__global__ __launch_bounds__(512) __cluster_dims__(2, 1, 1)
void fps_kernel(const float* __restrict__ xyz, float* __restrict__ out_xyz) {
    const int b = blockIdx.x >> 1;
    const int t = threadIdx.x;
    const int lane = t & 31;
    const int warp = t >> 5;
    const float* X = xyz + (size_t)b * NN * 3;

    uint32_t rank;
    asm("mov.u32 %0, %%cluster_ctarank;" : "=r"(rank));
    const int base = (int)rank * 4096;

    // 8 points/thread: pair p = (base + t + 2p*512, base + t + (2p+1)*512)
    ull px2[4], py2[4], pz2[4];
    float dd[8];
#pragma unroll
    for (int p = 0; p < 4; p++) {
        int i0 = base + t + (p << 10);
        int i1 = i0 + 512;
        px2[p] = f2pack(X[i0 * 3 + 0], X[i1 * 3 + 0]);
        py2[p] = f2pack(X[i0 * 3 + 1], X[i1 * 3 + 1]);
        pz2[p] = f2pack(X[i0 * 3 + 2], X[i1 * 3 + 2]);
        dd[2 * p] = 1e10f;
        dd[2 * p + 1] = 1e10f;
    }

    __shared__ unsigned sdist[2][16];
    __shared__ unsigned sidx[2][16];
    __shared__ ull recvs[2];
    __shared__ alignas(8) ull mbar_store;

    const uint32_t mbar = smem_u32(&mbar_store);
    const uint32_t slot0 = smem_u32(&recvs[0]);

    if (t == 0) {
        MBAR_INIT(mbar, 1);
    }
    asm volatile("fence.proxy.async.shared::cta;" ::: "memory");
    // cluster sync: peer must see our mbarrier initialized before st.async
    asm volatile("barrier.cluster.arrive.aligned;" ::: "memory");
    asm volatile("barrier.cluster.wait.aligned;" ::: "memory");

    const uint32_t peer = rank ^ 1u;
    uint32_t r_slot, r_mbar;
    asm("mapa.shared::cluster.u32 %0, %1, %2;" : "=r"(r_slot) : "r"(slot0), "r"(peer));
    asm("mapa.shared::cluster.u32 %0, %1, %2;" : "=r"(r_mbar) : "r"(mbar), "r"(peer));

    float lx = X[0], ly = X[1], lz = X[2];  // first centroid = point 0
    if (rank == 0 && t == 0) {
        float* o = out_xyz + (size_t)b * MM * 3;
        o[0] = lx; o[1] = ly; o[2] = lz;
    }

    for (int s = 1; s < MM; s++) {
        const ull nlx = f2pack(-lx, -lx);
        const ull nly = f2pack(-ly, -ly);
        const ull nlz = f2pack(-lz, -lz);
        float bestd = -1.0f;
        int besti = 0;
#pragma unroll
        for (int p = 0; p < 4; p++) {
            ull dx = add2(px2[p], nlx);  // x + (-c) == x - c exactly
            ull dy = add2(py2[p], nly);
            ull dz = add2(pz2[p], nlz);
            ull xx = mul2(dx, dx);
            ull yy = mul2(dy, dy);
            ull zz = mul2(dz, dz);
            ull ss = add2(add2(xx, yy), zz);  // ((dx²+dy²)+dz²) per lane
            float s0, s1;
            f2unpack(s0, s1, ss);
            float n0 = fminf(dd[2 * p], s0);
            dd[2 * p] = n0;
            if (n0 > bestd) { bestd = n0; besti = base + t + (p << 10); }
            float n1 = fminf(dd[2 * p + 1], s1);
            dd[2 * p + 1] = n1;
            if (n1 > bestd) { bestd = n1; besti = base + t + (p << 10) + 512; }
        }
        // warp argmax (dists >= 0 -> uint order == float order)
        unsigned bd = __float_as_uint(bestd);
        unsigned mx = __reduce_max_sync(0xffffffffu, bd);
        unsigned cand = (bd == mx) ? (unsigned)besti : 0xffffffffu;
        unsigned wsel = __reduce_min_sync(0xffffffffu, cand);
        if (lane == 0) {
            sdist[s & 1][warp] = mx;
            sidx[s & 1][warp] = wsel;
        }
        __syncthreads();
        unsigned d2 = sdist[s & 1][lane & 15];
        unsigned i2 = sidx[s & 1][lane & 15];
        unsigned mx2 = __reduce_max_sync(0xffffffffu, d2);
        unsigned cand2 = (d2 == mx2) ? i2 : 0xffffffffu;
        unsigned lsel = __reduce_min_sync(0xffffffffu, cand2);
        ull lkey = ((ull)mx2 << 32) | (unsigned)(NN - 1 - (int)lsel);

        // exchange with peer CTA
        if (t == 0) {
            MBAR_EXPECT_TX(mbar, 8u);
            uint32_t dst = r_slot + ((s & 1) << 3);
            asm volatile(
                "st.async.shared::cluster.mbarrier::complete_tx::bytes.b64 [%0], %1, [%2];"
                :: "r"(dst), "l"(lkey), "r"(r_mbar) : "memory");
        }
        MBAR_WAIT_PARITY(mbar, (s - 1) & 1);
        ull rkey = recvs[s & 1];
        ull wk = (rkey > lkey) ? rkey : lkey;
        int sel = (NN - 1) - (int)(unsigned)(wk & 0xffffffffULL);

        lx = __ldg(X + sel * 3 + 0);
        ly = __ldg(X + sel * 3 + 1);
        lz = __ldg(X + sel * 3 + 2);
        if (rank == 0 && t == 0) {
            float* o = out_xyz + ((size_t)b * MM + s) * 3;
            o[0] = lx; o[1] = ly; o[2] = lz;
        }
    }
}

// ---------------------------------------------------------------------------
// Kernel 2: ball query — one warp per query point, first-32 hits in index
// order, padded with the first hit.
// ---------------------------------------------------------------------------
__global__ __launch_bounds__(256) void ballq_kernel(const float* __restrict__ xyz,
                                                    const float* __restrict__ new_xyz) {
    const int w = (blockIdx.x * blockDim.x + threadIdx.x) >> 5;
    const int lane = threadIdx.x & 31;
    if (w >= BB * MM) return;
    const int b = w >> 10;
    const float* X = xyz + (size_t)b * NN * 3;
    const float cx = new_xyz[w * 3 + 0];
    const float cy = new_xyz[w * 3 + 1];
    const float cz = new_xyz[w * 3 + 2];
    const float R2 = (float)(0.4 * 0.4);  // NOT 0.4f*0.4f (one ulp apart)

    int cnt = 0;
    int first = -1;
    int* out = g_gidx + (size_t)w * KK;

    for (int base = 0; base < NN && cnt < KK; base += 32) {
        int i = base + lane;
        float x = X[i * 3 + 0], y = X[i * 3 + 1], z = X[i * 3 + 2];
        float dx = __fadd_rn(x, -cx);
        float dy = __fadd_rn(y, -cy);
        float dz = __fadd_rn(z, -cz);
        float d2 = __fadd_rn(__fadd_rn(__fmul_rn(dx, dx), __fmul_rn(dy, dy)),
                             __fmul_rn(dz, dz));
        bool hit = d2 < R2;
        unsigned msk = __ballot_sync(0xffffffffu, hit);
        if (msk) {
            if (first < 0) first = base + __ffs(msk) - 1;
            int pos = cnt + __popc(msk & ((1u << lane) - 1u));
            if (hit && pos < KK) out[pos] = i;
            cnt += __popc(msk);
        }
    }
    if (cnt < KK) {
        for (int s2 = cnt + lane; s2 < KK; s2 += 32) out[s2] = first;
    }
}

// ---------------------------------------------------------------------------
// Kernel 3: fused gather + MLP + maxpool. One WARP per (b,m) group,
// 8 groups per 256-thread block. x/h stored [c][k]-transposed in warp-private
// smem so k-pairs load as v2.u64 (zero pack instructions for x). 8k x 8o
// register tiles with k-packed f32x2 accumulators: per c, 4 LDS.128 + 8 packs
// + 32 fma2 for 64 FMA lanes. No block barriers in the hot loop.
// ---------------------------------------------------------------------------
__global__ __launch_bounds__(256) void mlp_kernel(
    const float* __restrict__ xyz, const float* __restrict__ feat,
    const float* __restrict__ w1, const float* __restrict__ b1,
    const float* __restrict__ w2, const float* __restrict__ b2,
    const float* __restrict__ w3, const float* __restrict__ b3,
    const float* __restrict__ new_xyz, float* __restrict__ out_feat) {
    extern __shared__ float sm[];
    float* w1t = sm;            // [67][64]
    float* w2t = sm + 4288;     // [64][64]
    float* w3t = sm + 8384;     // [64][128]
    float* b1s = sm + 16576;
    float* b2s = sm + 16640;
    float* b3s = sm + 16704;
    const int tid = threadIdx.x;
    const int warp = tid >> 5;
    const int lane = tid & 31;
    float* xs = sm + 16832 + warp * 4192;  // [67][32], reused as h2 [64][32]
    float* h1 = xs + 2144;                 // [64][32]

    // cooperative transposed weight load
    for (int e = tid; e < NH1 * CIN; e += 256) {
        int o = e / CIN, c = e - o * CIN;
        w1t[c * 64 + o] = w1[e];
    }
    for (int e = tid; e < NH2 * NH1; e += 256) {
        int o = e >> 6, c = e & 63;
        w2t[c * 64 + o] = w2[e];
    }
    for (int e = tid; e < NH3 * NH2; e += 256) {
        int o = e >> 6, c = e & 63;
        w3t[c * 128 + o] = w3[e];
    }
    if (tid < 64) b1s[tid] = b1[tid];
    else if (tid < 128) b2s[tid - 64] = b2[tid - 64];
    else b3s[tid - 128] = b3[tid - 128];
    __syncthreads();

    const int g = blockIdx.x * 8 + warp;
    const int b = g >> 10;
    const int m = g & 1023;
    const float* Xb = xyz + (size_t)b * NN * 3;
    const float* Fb = feat + (size_t)b * NN * 64;

    // gather: lane handles neighbor k=lane, writes [c][k] transposed
    {
        const int gi = g_gidx[(size_t)g * KK + lane];
        const float cx = new_xyz[g * 3 + 0];
        const float cy = new_xyz[g * 3 + 1];
        const float cz = new_xyz[g * 3 + 2];
        xs[0 * 32 + lane] = Xb[gi * 3 + 0] - cx;
        xs[1 * 32 + lane] = Xb[gi * 3 + 1] - cy;
        xs[2 * 32 + lane] = Xb[gi * 3 + 2] - cz;
        const float4* fr = (const float4*)(Fb + (size_t)gi * 64);
#pragma unroll
        for (int q = 0; q < 16; q++) {
            float4 v = fr[q];
            xs[(3 + 4 * q + 0) * 32 + lane] = v.x;
            xs[(3 + 4 * q + 1) * 32 + lane] = v.y;
            xs[(3 + 4 * q + 2) * 32 + lane] = v.z;
            xs[(3 + 4 * q + 3) * 32 + lane] = v.w;
        }
    }
    __syncwarp();

    const int kt = lane & 3;   // 4 k-tiles of 8
    const int ot = lane >> 2;  // 8 o-tiles of 8

    ull acc[8][4];

    // ---- layer 1: 67 -> 64 ----
#pragma unroll
    for (int j = 0; j < 8; j++) {
        float bb = b1s[ot * 8 + j];
        ull bp = f2pack(bb, bb);
#pragma unroll
        for (int p = 0; p < 4; p++) acc[j][p] = bp;
    }
    for (int c = 0; c < CIN; c++) {
        ulonglong2 xA = *(const ulonglong2*)&xs[c * 32 + kt * 8];
        ulonglong2 xB = *(const ulonglong2*)&xs[c * 32 + kt * 8 + 4];
        ull xp[4] = {xA.x, xA.y, xB.x, xB.y};
        float4 wA = *(const float4*)&w1t[c * 64 + ot * 8];
        float4 wB = *(const float4*)&w1t[c * 64 + ot * 8 + 4];
        float wf[8] = {wA.x, wA.y, wA.z, wA.w, wB.x, wB.y, wB.z, wB.w};
#pragma unroll
        for (int j = 0; j < 8; j++) {
            ull wd = f2pack(wf[j], wf[j]);
#pragma unroll
            for (int p = 0; p < 4; p++) acc[j][p] = fma2(xp[p], wd, acc[j][p]);
        }
    }
#pragma unroll
    for (int j = 0; j < 8; j++) {
        float r[8];
#pragma unroll
        for (int p = 0; p < 4; p++) f2unpack(r[2 * p], r[2 * p + 1], acc[j][p]);
        float4 v0 = make_float4(fmaxf(r[0], 0.f), fmaxf(r[1], 0.f), fmaxf(r[2], 0.f), fmaxf(r[3], 0.f));
        float4 v1 = make_float4(fmaxf(r[4], 0.f), fmaxf(r[5], 0.f), fmaxf(r[6], 0.f), fmaxf(r[7], 0.f));
        *(float4*)&h1[(ot * 8 + j) * 32 + kt * 8] = v0;
        *(float4*)&h1[(ot * 8 + j) * 32 + kt * 8 + 4] = v1;
    }
    __syncwarp();

    // ---- layer 2: 64 -> 64 (reads h1, writes h2 into xs) ----
#pragma unroll
    for (int j = 0; j < 8; j++) {
        float bb = b2s[ot * 8 + j];
        ull bp = f2pack(bb, bb);
#pragma unroll
        for (int p = 0; p < 4; p++) acc[j][p] = bp;
    }
    for (int c = 0; c < NH1; c++) {
        ulonglong2 xA = *(const ulonglong2*)&h1[c * 32 + kt * 8];
        ulonglong2 xB = *(const ulonglong2*)&h1[c * 32 + kt * 8 + 4];
        ull xp[4] = {xA.x, xA.y, xB.x, xB.y};
        float4 wA = *(const float4*)&w2t[c * 64 + ot * 8];
        float4 wB = *(const float4*)&w2t[c * 64 + ot * 8 + 4];
        float wf[8] = {wA.x, wA.y, wA.z, wA.w, wB.x, wB.y, wB.z, wB.w};
#pragma unroll
        for (int j = 0; j < 8; j++) {
            ull wd = f2pack(wf[j], wf[j]);
#pragma unroll
            for (int p = 0; p < 4; p++) acc[j][p] = fma2(xp[p], wd, acc[j][p]);
        }
    }
    __syncwarp();  // xs (layer-1 input) dead for all lanes before overwrite
#pragma unroll
    for (int j = 0; j < 8; j++) {
        float r[8];
#pragma unroll
        for (int p = 0; p < 4; p++) f2unpack(r[2 * p], r[2 * p + 1], acc[j][p]);
        float4 v0 = make_float4(fmaxf(r[0], 0.f), fmaxf(r[1], 0.f), fmaxf(r[2], 0.f), fmaxf(r[3], 0.f));
        float4 v1 = make_float4(fmaxf(r[4], 0.f), fmaxf(r[5], 0.f), fmaxf(r[6], 0.f), fmaxf(r[7], 0.f));
        *(float4*)&xs[(ot * 8 + j) * 32 + kt * 8] = v0;
        *(float4*)&xs[(ot * 8 + j) * 32 + kt * 8 + 4] = v1;
    }
    __syncwarp();

    // ---- layer 3: 64 -> 128 in two o-halves, then max over k ----
    for (int h = 0; h < 2; h++) {
#pragma unroll
        for (int j = 0; j < 8; j++) {
            float bb = b3s[h * 64 + ot * 8 + j];
            ull bp = f2pack(bb, bb);
#pragma unroll
            for (int p = 0; p < 4; p++) acc[j][p] = bp;
        }
        for (int c = 0; c < NH2; c++) {
            ulonglong2 xA = *(const ulonglong2*)&xs[c * 32 + kt * 8];
            ulonglong2 xB = *(const ulonglong2*)&xs[c * 32 + kt * 8 + 4];
            ull xp[4] = {xA.x, xA.y, xB.x, xB.y};
            float4 wA = *(const float4*)&w3t[c * 128 + h * 64 + ot * 8];
            float4 wB = *(const float4*)&w3t[c * 128 + h * 64 + ot * 8 + 4];
            float wf[8] = {wA.x, wA.y, wA.z, wA.w, wB.x, wB.y, wB.z, wB.w};
#pragma unroll
            for (int j = 0; j < 8; j++) {
                ull wd = f2pack(wf[j], wf[j]);
#pragma unroll
                for (int p = 0; p < 4; p++) acc[j][p] = fma2(xp[p], wd, acc[j][p]);
            }
        }
        float v[8];
#pragma unroll
        for (int j = 0; j < 8; j++) {
            float r[8];
#pragma unroll
            for (int p = 0; p < 4; p++) f2unpack(r[2 * p], r[2 * p + 1], acc[j][p]);
            float mx = fmaxf(fmaxf(fmaxf(r[0], r[1]), fmaxf(r[2], r[3])),
                             fmaxf(fmaxf(r[4], r[5]), fmaxf(r[6], r[7])));
            v[j] = fmaxf(mx, 0.0f);  // relu commutes with max
        }
        // reduce across kt (lane bits 0..1)
#pragma unroll
        for (int d = 1; d < 4; d <<= 1)
#pragma unroll
            for (int j = 0; j < 8; j++)
                v[j] = fmaxf(v[j], __shfl_xor_sync(0xffffffffu, v[j], d));
        if (kt == 0) {
#pragma unroll
            for (int j = 0; j < 8; j++)
                out_feat[((size_t)b * NH3 + h * 64 + ot * 8 + j) * MM + m] = v[j];
        }
    }
}

// ---------------------------------------------------------------------------
extern "C" void kernel_launch(void* const* d_in, const int* in_sizes, int n_in,
                              void* d_out, int out_size) {
    const float* xyz = (const float*)d_in[0];
    const float* feat = (const float*)d_in[1];
    const float* w1 = (const float*)d_in[2];
    const float* b1 = (const float*)d_in[3];
    const float* w2 = (const float*)d_in[4];
    const float* b2 = (const float*)d_in[5];
    const float* w3 = (const float*)d_in[6];
    const float* b3 = (const float*)d_in[7];

    float* out = (float*)d_out;
    float* out_xyz = out;                 // (8,1024,3)
    float* out_feat = out + BB * MM * 3;  // (8,128,1024)

    fps_kernel<<<BB * 2, 512>>>(xyz, out_xyz);
    ballq_kernel<<<(BB * MM * 32) / 256, 256>>>(xyz, out_xyz);

    const int smem_bytes = 50368 * 4;  // 201472 B
    cudaFuncSetAttribute(mlp_kernel, cudaFuncAttributeMaxDynamicSharedMemorySize,
                         smem_bytes);
    mlp_kernel<<<BB * MM / 8, 256, smem_bytes>>>(xyz, feat, w1, b1, w2, b2, w3, b3,
                                                 out_xyz, out_feat);
}

// round 5
// speedup vs baseline: 1.7511x; 1.0465x over previous
#include <cuda_runtime.h>
#include <cstddef>
#include <cstdint>

#define BB 8
#define NN 8192
#define MM 1024
#define KK 32
#define CIN 67
#define NH1 64
#define NH2 64
#define NH3 128

typedef unsigned long long ull;

__device__ __forceinline__ ull f2pack(float lo, float hi) {
    ull r; asm("mov.b64 %0,{%1,%2};" : "=l"(r) : "f"(lo), "f"(hi)); return r;
}
__device__ __forceinline__ void f2unpack(float& lo, float& hi, ull v) {
    asm("mov.b64 {%0,%1},%2;" : "=f"(lo), "=f"(hi) : "l"(v));
}
__device__ __forceinline__ ull add2(ull a, ull b) {
    ull r; asm("add.rn.f32x2 %0,%1,%2;" : "=l"(r) : "l"(a), "l"(b)); return r;
}
__device__ __forceinline__ ull mul2(ull a, ull b) {
    ull r; asm("mul.rn.f32x2 %0,%1,%2;" : "=l"(r) : "l"(a), "l"(b)); return r;
}
__device__ __forceinline__ ull fma2(ull a, ull b, ull c) {
    ull r; asm("fma.rn.f32x2 %0,%1,%2,%3;" : "=l"(r) : "l"(a), "l"(b), "l"(c)); return r;
}
__device__ __forceinline__ uint32_t smem_u32(const void* p) {
    uint32_t a;
    asm("{ .reg .u64 t; cvta.to.shared.u64 t, %1; cvt.u32.u64 %0, t; }" : "=r"(a) : "l"(p));
    return a;
}

#define MBAR_INIT(addr, cnt) \
    asm volatile("mbarrier.init.shared.b64 [%0], %1;" :: "r"(addr), "r"(cnt) : "memory")
#define MBAR_EXPECT_TX(addr, bytes) \
    asm volatile("mbarrier.arrive.expect_tx.shared.b64 _, [%0], %1;" :: "r"(addr), "r"(bytes) : "memory")
// cluster-scope acquire: the data we read after the wait was written by the
// peer CTA's st.async.
#define MBAR_WAIT_PARITY_CLU(addr, par) do { \
    uint32_t _m = (addr); uint32_t _p = (par); uint32_t _d; \
    asm volatile("{\n\t.reg .pred p;\n\t" \
        "mbarrier.try_wait.parity.acquire.cluster.shared::cta.b64 p, [%1], %2;\n\t" \
        "selp.b32 %0, 1, 0, p;\n\t}" : "=r"(_d) : "r"(_m), "r"(_p) : "memory"); \
    if (!_d) { \
        asm volatile("{\n\t.reg .pred P1;\n\t" \
            "WL_%=:\n\t" \
            "mbarrier.try_wait.parity.acquire.cluster.shared::cta.b64 P1, [%0], %1, 0x989680;\n\t" \
            "@P1 bra.uni WD_%=;\n\t" \
            "bra.uni WL_%=;\n\t" \
            "WD_%=:\n\t}" :: "r"(_m), "r"(_p) : "memory"); \
    } \
} while (0)

// scratch: ball-query neighbor indices (B*M*K)
__device__ int g_gidx[BB * MM * KK];

// ---------------------------------------------------------------------------
// Kernel 1: FPS, 2-CTA cluster per batch, 512 thr x 8 pts, bit-exact f32x2
// distance math. Exchange is per-WARP: each warp st.asyncs its warp key to the
// peer right after its warp redux, so the ~215-cyc DSMEM transit overlaps the
// local STS + __syncthreads. Final: one warp-width redux over 32 keys
// (16 local + 16 remote). Key = (distbits, idx); max-dist then min-idx
// tie-break == jnp.argmax first-max semantics.
// ---------------------------------------------------------------------------
__global__ __launch_bounds__(512) __cluster_dims__(2, 1, 1)
void fps_kernel(const float* __restrict__ xyz, float* __restrict__ out_xyz) {
    const int b = blockIdx.x >> 1;
    const int t = threadIdx.x;
    const int lane = t & 31;
    const int warp = t >> 5;
    const float* X = xyz + (size_t)b * NN * 3;

    uint32_t rank;
    asm("mov.u32 %0, %%cluster_ctarank;" : "=r"(rank));
    const int base = (int)rank * 4096;

    ull px2[4], py2[4], pz2[4];
    float dd[8];
#pragma unroll
    for (int p = 0; p < 4; p++) {
        int i0 = base + t + (p << 10);
        int i1 = i0 + 512;
        px2[p] = f2pack(X[i0 * 3 + 0], X[i1 * 3 + 0]);
        py2[p] = f2pack(X[i0 * 3 + 1], X[i1 * 3 + 1]);
        pz2[p] = f2pack(X[i0 * 3 + 2], X[i1 * 3 + 2]);
        dd[2 * p] = 1e10f;
        dd[2 * p + 1] = 1e10f;
    }

    __shared__ alignas(16) ull keyu[2][32];  // [parity][slot]; 0-15 local, 16-31 remote
    __shared__ alignas(8) ull mbar_store;

    const uint32_t mbar = smem_u32(&mbar_store);
    const uint32_t keybase = smem_u32(&keyu[0][0]);

    if (t == 0) MBAR_INIT(mbar, 1);
    asm volatile("fence.proxy.async.shared::cta;" ::: "memory");
    asm volatile("barrier.cluster.arrive.aligned;" ::: "memory");
    asm volatile("barrier.cluster.wait.aligned;" ::: "memory");

    const uint32_t peer = rank ^ 1u;
    uint32_t r_key, r_mbar;
    asm("mapa.shared::cluster.u32 %0, %1, %2;" : "=r"(r_key) : "r"(keybase), "r"(peer));
    asm("mapa.shared::cluster.u32 %0, %1, %2;" : "=r"(r_mbar) : "r"(mbar), "r"(peer));

    float lx = X[0], ly = X[1], lz = X[2];  // first centroid = point 0
    if (rank == 0 && t == 0) {
        float* o = out_xyz + (size_t)b * MM * 3;
        o[0] = lx; o[1] = ly; o[2] = lz;
    }

    for (int s = 1; s < MM; s++) {
        if (t == 0) MBAR_EXPECT_TX(mbar, 128u);  // credits current phase (s-1)

        const ull nlx = f2pack(-lx, -lx);
        const ull nly = f2pack(-ly, -ly);
        const ull nlz = f2pack(-lz, -lz);
        float bestd = -1.0f;
        int besti = 0;
#pragma unroll
        for (int p = 0; p < 4; p++) {
            ull dx = add2(px2[p], nlx);  // x + (-c) == x - c exactly
            ull dy = add2(py2[p], nly);
            ull dz = add2(pz2[p], nlz);
            ull xx = mul2(dx, dx);
            ull yy = mul2(dy, dy);
            ull zz = mul2(dz, dz);
            ull ss = add2(add2(xx, yy), zz);  // ((dx²+dy²)+dz²)
            float s0, s1;
            f2unpack(s0, s1, ss);
            float n0 = fminf(dd[2 * p], s0);
            dd[2 * p] = n0;
            if (n0 > bestd) { bestd = n0; besti = base + t + (p << 10); }
            float n1 = fminf(dd[2 * p + 1], s1);
            dd[2 * p + 1] = n1;
            if (n1 > bestd) { bestd = n1; besti = base + t + (p << 10) + 512; }
        }
        // warp argmax (dists >= 0 -> uint order == float order), min-idx tie-break
        unsigned bd = __float_as_uint(bestd);
        unsigned mx = __reduce_max_sync(0xffffffffu, bd);
        unsigned cand = (bd == mx) ? (unsigned)besti : 0xffffffffu;
        unsigned wsel = __reduce_min_sync(0xffffffffu, cand);
        if (lane == 0) {
            ull key = ((ull)mx << 32) | wsel;
            keyu[s & 1][warp] = key;  // local slot
            uint32_t dst = r_key + (((s & 1) << 5) + 16 + warp) * 8;  // peer slot
            asm volatile(
                "st.async.shared::cluster.mbarrier::complete_tx::bytes.b64 [%0], %1, [%2];"
                :: "r"(dst), "l"(key), "r"(r_mbar) : "memory");
        }
        __syncthreads();                       // local 16 keys visible
        MBAR_WAIT_PARITY_CLU(mbar, (s - 1) & 1);  // remote 16 keys arrived

        ull k2 = keyu[s & 1][lane];
        unsigned d2 = (unsigned)(k2 >> 32);
        unsigned i2 = (unsigned)k2;
        unsigned mx2 = __reduce_max_sync(0xffffffffu, d2);
        unsigned cand2 = (d2 == mx2) ? i2 : 0xffffffffu;
        int sel = (int)__reduce_min_sync(0xffffffffu, cand2);

        lx = __ldg(X + sel * 3 + 0);
        ly = __ldg(X + sel * 3 + 1);
        lz = __ldg(X + sel * 3 + 2);
        if (rank == 0 && t == 0) {
            float* o = out_xyz + ((size_t)b * MM + s) * 3;
            o[0] = lx; o[1] = ly; o[2] = lz;
        }
    }
}

// ---------------------------------------------------------------------------
// Kernel 2: ball query — one warp per query point, first-32 hits in index
// order, padded with the first hit.
// ---------------------------------------------------------------------------
__global__ __launch_bounds__(256) void ballq_kernel(const float* __restrict__ xyz,
                                                    const float* __restrict__ new_xyz) {
    const int w = (blockIdx.x * blockDim.x + threadIdx.x) >> 5;
    const int lane = threadIdx.x & 31;
    if (w >= BB * MM) return;
    const int b = w >> 10;
    const float* X = xyz + (size_t)b * NN * 3;
    const float cx = new_xyz[w * 3 + 0];
    const float cy = new_xyz[w * 3 + 1];
    const float cz = new_xyz[w * 3 + 2];
    const float R2 = (float)(0.4 * 0.4);  // NOT 0.4f*0.4f (one ulp apart)

    int cnt = 0;
    int first = -1;
    int* out = g_gidx + (size_t)w * KK;

    for (int base = 0; base < NN && cnt < KK; base += 32) {
        int i = base + lane;
        float x = X[i * 3 + 0], y = X[i * 3 + 1], z = X[i * 3 + 2];
        float dx = __fadd_rn(x, -cx);
        float dy = __fadd_rn(y, -cy);
        float dz = __fadd_rn(z, -cz);
        float d2 = __fadd_rn(__fadd_rn(__fmul_rn(dx, dx), __fmul_rn(dy, dy)),
                             __fmul_rn(dz, dz));
        bool hit = d2 < R2;
        unsigned msk = __ballot_sync(0xffffffffu, hit);
        if (msk) {
            if (first < 0) first = base + __ffs(msk) - 1;
            int pos = cnt + __popc(msk & ((1u << lane) - 1u));
            if (hit && pos < KK) out[pos] = i;
            cnt += __popc(msk);
        }
    }
    if (cnt < KK) {
        for (int s2 = cnt + lane; s2 < KK; s2 += 32) out[s2] = first;
    }
}

// ---------------------------------------------------------------------------
// Kernel 3: fused gather + MLP + maxpool. 512 threads = 16 warps = 8 groups
// x 2 warps; the 2 warps of a group split the OUTPUT dim (32/64 each, 64/128
// in layer 3) and share the group's [c][k] buffers. Per-group named barriers
// (bar.sync id,64) keep groups decoupled -> 4 warps/SMSP latency hiding at
// the same 201 KB smem as R4.
// ---------------------------------------------------------------------------
__global__ __launch_bounds__(512) void mlp_kernel(
    const float* __restrict__ xyz, const float* __restrict__ feat,
    const float* __restrict__ w1, const float* __restrict__ b1,
    const float* __restrict__ w2, const float* __restrict__ b2,
    const float* __restrict__ w3, const float* __restrict__ b3,
    const float* __restrict__ new_xyz, float* __restrict__ out_feat) {
    extern __shared__ float sm[];
    float* w1t = sm;            // [67][64]
    float* w2t = sm + 4288;     // [64][64]
    float* w3t = sm + 8384;     // [64][128]
    float* b1s = sm + 16576;
    float* b2s = sm + 16640;
    float* b3s = sm + 16704;
    const int tid = threadIdx.x;
    const int lane = tid & 31;
    const int grp = tid >> 6;        // 8 groups
    const int w2id = (tid >> 5) & 1; // warp within group: o-half
    const int gt = tid & 63;         // thread within group
    float* xs = sm + 16832 + grp * 4192;  // [67][32], reused as h2 [64][32]
    float* h1 = xs + 2144;                // [64][32]

    // cooperative transposed weight load
    for (int e = tid; e < NH1 * CIN; e += 512) {
        int o = e / CIN, c = e - o * CIN;
        w1t[c * 64 + o] = w1[e];
    }
    for (int e = tid; e < NH2 * NH1; e += 512) {
        int o = e >> 6, c = e & 63;
        w2t[c * 64 + o] = w2[e];
    }
    for (int e = tid; e < NH3 * NH2; e += 512) {
        int o = e >> 6, c = e & 63;
        w3t[c * 128 + o] = w3[e];
    }
    if (tid < 64) b1s[tid] = b1[tid];
    else if (tid < 128) b2s[tid - 64] = b2[tid - 64];
    else if (tid < 256) b3s[tid - 128] = b3[tid - 128];
    __syncthreads();

    const int g = blockIdx.x * 8 + grp;
    const int b = g >> 10;
    const int m = g & 1023;
    const float* Xb = xyz + (size_t)b * NN * 3;
    const float* Fb = feat + (size_t)b * NN * 64;
    const int barid = grp + 1;

    // gather: 64 threads, k = gt&31; half 0 -> rel-xyz + feats 0..31,
    // half 1 -> feats 32..63. Layout [c][k].
    {
        const int k = gt & 31;
        const int fh = gt >> 5;
        const int gi = g_gidx[(size_t)g * KK + k];
        if (fh == 0) {
            xs[0 * 32 + k] = Xb[gi * 3 + 0] - new_xyz[g * 3 + 0];
            xs[1 * 32 + k] = Xb[gi * 3 + 1] - new_xyz[g * 3 + 1];
            xs[2 * 32 + k] = Xb[gi * 3 + 2] - new_xyz[g * 3 + 2];
        }
        const float4* fr = (const float4*)(Fb + (size_t)gi * 64 + fh * 32);
#pragma unroll
        for (int q = 0; q < 8; q++) {
            float4 v = fr[q];
            int c = 3 + fh * 32 + 4 * q;
            xs[(c + 0) * 32 + k] = v.x;
            xs[(c + 1) * 32 + k] = v.y;
            xs[(c + 2) * 32 + k] = v.z;
            xs[(c + 3) * 32 + k] = v.w;
        }
    }
    asm volatile("bar.sync %0, 64;" :: "r"(barid) : "memory");

    const int kt = lane & 3;   // 4 k-tiles of 8
    const int ot = lane >> 2;  // 8 o-tiles
    const int ob = w2id * 32 + ot * 4;  // layers 1/2: 4 outputs per lane

    // ---- layer 1: 67 -> 64 (this warp: 32 of 64 outputs) ----
    {
        ull acc[4][4];
#pragma unroll
        for (int j = 0; j < 4; j++) {
            float bb = b1s[ob + j];
            ull bp = f2pack(bb, bb);
#pragma unroll
            for (int p = 0; p < 4; p++) acc[j][p] = bp;
        }
        for (int c = 0; c < CIN; c++) {
            ulonglong2 xA = *(const ulonglong2*)&xs[c * 32 + kt * 8];
            ulonglong2 xB = *(const ulonglong2*)&xs[c * 32 + kt * 8 + 4];
            ull xp[4] = {xA.x, xA.y, xB.x, xB.y};
            float4 wv = *(const float4*)&w1t[c * 64 + ob];
            float wf[4] = {wv.x, wv.y, wv.z, wv.w};
#pragma unroll
            for (int j = 0; j < 4; j++) {
                ull wd = f2pack(wf[j], wf[j]);
#pragma unroll
                for (int p = 0; p < 4; p++) acc[j][p] = fma2(xp[p], wd, acc[j][p]);
            }
        }
#pragma unroll
        for (int j = 0; j < 4; j++) {
            float r[8];
#pragma unroll
            for (int p = 0; p < 4; p++) f2unpack(r[2 * p], r[2 * p + 1], acc[j][p]);
            float4 v0 = make_float4(fmaxf(r[0], 0.f), fmaxf(r[1], 0.f), fmaxf(r[2], 0.f), fmaxf(r[3], 0.f));
            float4 v1 = make_float4(fmaxf(r[4], 0.f), fmaxf(r[5], 0.f), fmaxf(r[6], 0.f), fmaxf(r[7], 0.f));
            *(float4*)&h1[(ob + j) * 32 + kt * 8] = v0;
            *(float4*)&h1[(ob + j) * 32 + kt * 8 + 4] = v1;
        }
    }
    asm volatile("bar.sync %0, 64;" :: "r"(barid) : "memory");

    // ---- layer 2: 64 -> 64 (reads h1, writes h2 into xs) ----
    {
        ull acc[4][4];
#pragma unroll
        for (int j = 0; j < 4; j++) {
            float bb = b2s[ob + j];
            ull bp = f2pack(bb, bb);
#pragma unroll
            for (int p = 0; p < 4; p++) acc[j][p] = bp;
        }
        for (int c = 0; c < NH1; c++) {
            ulonglong2 xA = *(const ulonglong2*)&h1[c * 32 + kt * 8];
            ulonglong2 xB = *(const ulonglong2*)&h1[c * 32 + kt * 8 + 4];
            ull xp[4] = {xA.x, xA.y, xB.x, xB.y};
            float4 wv = *(const float4*)&w2t[c * 64 + ob];
            float wf[4] = {wv.x, wv.y, wv.z, wv.w};
#pragma unroll
            for (int j = 0; j < 4; j++) {
                ull wd = f2pack(wf[j], wf[j]);
#pragma unroll
                for (int p = 0; p < 4; p++) acc[j][p] = fma2(xp[p], wd, acc[j][p]);
            }
        }
        // xs (layer-1 input) dead after layer-1 barrier; safe to overwrite
#pragma unroll
        for (int j = 0; j < 4; j++) {
            float r[8];
#pragma unroll
            for (int p = 0; p < 4; p++) f2unpack(r[2 * p], r[2 * p + 1], acc[j][p]);
            float4 v0 = make_float4(fmaxf(r[0], 0.f), fmaxf(r[1], 0.f), fmaxf(r[2], 0.f), fmaxf(r[3], 0.f));
            float4 v1 = make_float4(fmaxf(r[4], 0.f), fmaxf(r[5], 0.f), fmaxf(r[6], 0.f), fmaxf(r[7], 0.f));
            *(float4*)&xs[(ob + j) * 32 + kt * 8] = v0;
            *(float4*)&xs[(ob + j) * 32 + kt * 8 + 4] = v1;
        }
    }
    asm volatile("bar.sync %0, 64;" :: "r"(barid) : "memory");

    // ---- layer 3: 64 -> 128 (this warp: 64 outputs, 8 per lane), maxpool ----
    {
        const int ob3 = w2id * 64 + ot * 8;
        ull acc[8][4];
#pragma unroll
        for (int j = 0; j < 8; j++) {
            float bb = b3s[ob3 + j];
            ull bp = f2pack(bb, bb);
#pragma unroll
            for (int p = 0; p < 4; p++) acc[j][p] = bp;
        }
        for (int c = 0; c < NH2; c++) {
            ulonglong2 xA = *(const ulonglong2*)&xs[c * 32 + kt * 8];
            ulonglong2 xB = *(const ulonglong2*)&xs[c * 32 + kt * 8 + 4];
            ull xp[4] = {xA.x, xA.y, xB.x, xB.y};
            float4 wA = *(const float4*)&w3t[c * 128 + ob3];
            float4 wB = *(const float4*)&w3t[c * 128 + ob3 + 4];
            float wf[8] = {wA.x, wA.y, wA.z, wA.w, wB.x, wB.y, wB.z, wB.w};
#pragma unroll
            for (int j = 0; j < 8; j++) {
                ull wd = f2pack(wf[j], wf[j]);
#pragma unroll
                for (int p = 0; p < 4; p++) acc[j][p] = fma2(xp[p], wd, acc[j][p]);
            }
        }
        float v[8];
#pragma unroll
        for (int j = 0; j < 8; j++) {
            float r[8];
#pragma unroll
            for (int p = 0; p < 4; p++) f2unpack(r[2 * p], r[2 * p + 1], acc[j][p]);
            float mx = fmaxf(fmaxf(fmaxf(r[0], r[1]), fmaxf(r[2], r[3])),
                             fmaxf(fmaxf(r[4], r[5]), fmaxf(r[6], r[7])));
            v[j] = fmaxf(mx, 0.0f);  // relu commutes with max
        }
#pragma unroll
        for (int d = 1; d < 4; d <<= 1)
#pragma unroll
            for (int j = 0; j < 8; j++)
                v[j] = fmaxf(v[j], __shfl_xor_sync(0xffffffffu, v[j], d));
        if (kt == 0) {
#pragma unroll
            for (int j = 0; j < 8; j++)
                out_feat[((size_t)b * NH3 + ob3 + j) * MM + m] = v[j];
        }
    }
}

// ---------------------------------------------------------------------------
extern "C" void kernel_launch(void* const* d_in, const int* in_sizes, int n_in,
                              void* d_out, int out_size) {
    const float* xyz = (const float*)d_in[0];
    const float* feat = (const float*)d_in[1];
    const float* w1 = (const float*)d_in[2];
    const float* b1 = (const float*)d_in[3];
    const float* w2 = (const float*)d_in[4];
    const float* b2 = (const float*)d_in[5];
    const float* w3 = (const float*)d_in[6];
    const float* b3 = (const float*)d_in[7];

    float* out = (float*)d_out;
    float* out_xyz = out;                 // (8,1024,3)
    float* out_feat = out + BB * MM * 3;  // (8,128,1024)

    fps_kernel<<<BB * 2, 512>>>(xyz, out_xyz);
    ballq_kernel<<<(BB * MM * 32) / 256, 256>>>(xyz, out_xyz);

    const int smem_bytes = 50368 * 4;  // 201472 B
    cudaFuncSetAttribute(mlp_kernel, cudaFuncAttributeMaxDynamicSharedMemorySize,
                         smem_bytes);
    mlp_kernel<<<BB * MM / 8, 512, smem_bytes>>>(xyz, feat, w1, b1, w2, b2, w3, b3,
                                                 out_xyz, out_feat);
}

// round 6
// speedup vs baseline: 1.8118x; 1.0346x over previous
#include <cuda_runtime.h>
#include <cstddef>
#include <cstdint>

#define BB 8
#define NN 8192
#define MM 1024
#define KK 32
#define CIN 67
#define NH1 64
#define NH2 64
#define NH3 128

typedef unsigned long long ull;

__device__ __forceinline__ ull f2pack(float lo, float hi) {
    ull r; asm("mov.b64 %0,{%1,%2};" : "=l"(r) : "f"(lo), "f"(hi)); return r;
}
__device__ __forceinline__ void f2unpack(float& lo, float& hi, ull v) {
    asm("mov.b64 {%0,%1},%2;" : "=f"(lo), "=f"(hi) : "l"(v));
}
__device__ __forceinline__ ull add2(ull a, ull b) {
    ull r; asm("add.rn.f32x2 %0,%1,%2;" : "=l"(r) : "l"(a), "l"(b)); return r;
}
__device__ __forceinline__ ull mul2(ull a, ull b) {
    ull r; asm("mul.rn.f32x2 %0,%1,%2;" : "=l"(r) : "l"(a), "l"(b)); return r;
}
__device__ __forceinline__ ull fma2(ull a, ull b, ull c) {
    ull r; asm("fma.rn.f32x2 %0,%1,%2,%3;" : "=l"(r) : "l"(a), "l"(b), "l"(c)); return r;
}
__device__ __forceinline__ uint32_t smem_u32(const void* p) {
    uint32_t a;
    asm("{ .reg .u64 t; cvta.to.shared.u64 t, %1; cvt.u32.u64 %0, t; }" : "=r"(a) : "l"(p));
    return a;
}

#define MBAR_INIT(addr, cnt) \
    asm volatile("mbarrier.init.shared.b64 [%0], %1;" :: "r"(addr), "r"(cnt) : "memory")
#define MBAR_EXPECT_TX(addr, bytes) \
    asm volatile("mbarrier.arrive.expect_tx.shared.b64 _, [%0], %1;" :: "r"(addr), "r"(bytes) : "memory")
#define MBAR_WAIT_PARITY_CLU(addr, par) do { \
    uint32_t _m = (addr); uint32_t _p = (par); uint32_t _d; \
    asm volatile("{\n\t.reg .pred p;\n\t" \
        "mbarrier.try_wait.parity.acquire.cluster.shared::cta.b64 p, [%1], %2;\n\t" \
        "selp.b32 %0, 1, 0, p;\n\t}" : "=r"(_d) : "r"(_m), "r"(_p) : "memory"); \
    if (!_d) { \
        asm volatile("{\n\t.reg .pred P1;\n\t" \
            "WL_%=:\n\t" \
            "mbarrier.try_wait.parity.acquire.cluster.shared::cta.b64 P1, [%0], %1, 0x989680;\n\t" \
            "@P1 bra.uni WD_%=;\n\t" \
            "bra.uni WL_%=;\n\t" \
            "WD_%=:\n\t}" :: "r"(_m), "r"(_p) : "memory"); \
    } \
} while (0)

// scratch: ball-query neighbor indices (B*M*K)
__device__ int g_gidx[BB * MM * KK];

// ---------------------------------------------------------------------------
// Kernel 1: FPS, 2-CTA cluster per batch, 512 thr x 8 pts, bit-exact f32x2
// distance math. Thread-local argmax via FMNMX tree + equality-match + IMNMX
// tree (no serial predicate chain). Per-warp keys exchanged with the peer CTA
// via st.async (overlapped with local STS + syncthreads).
// ---------------------------------------------------------------------------
__global__ __launch_bounds__(512) __cluster_dims__(2, 1, 1)
void fps_kernel(const float* __restrict__ xyz, float* __restrict__ out_xyz) {
    const int b = blockIdx.x >> 1;
    const int t = threadIdx.x;
    const int lane = t & 31;
    const int warp = t >> 5;
    const float* X = xyz + (size_t)b * NN * 3;

    uint32_t rank;
    asm("mov.u32 %0, %%cluster_ctarank;" : "=r"(rank));
    const int base = (int)rank * 4096;

    ull px2[4], py2[4], pz2[4];
    float dd[8];
#pragma unroll
    for (int p = 0; p < 4; p++) {
        int i0 = base + t + (p << 10);
        int i1 = i0 + 512;
        px2[p] = f2pack(X[i0 * 3 + 0], X[i1 * 3 + 0]);
        py2[p] = f2pack(X[i0 * 3 + 1], X[i1 * 3 + 1]);
        pz2[p] = f2pack(X[i0 * 3 + 2], X[i1 * 3 + 2]);
        dd[2 * p] = 1e10f;
        dd[2 * p + 1] = 1e10f;
    }

    __shared__ alignas(16) ull keyu[2][32];  // [parity][slot]; 0-15 local, 16-31 remote
    __shared__ alignas(8) ull mbar_store;

    const uint32_t mbar = smem_u32(&mbar_store);
    const uint32_t keybase = smem_u32(&keyu[0][0]);

    if (t == 0) MBAR_INIT(mbar, 1);
    asm volatile("fence.proxy.async.shared::cta;" ::: "memory");
    asm volatile("barrier.cluster.arrive.aligned;" ::: "memory");
    asm volatile("barrier.cluster.wait.aligned;" ::: "memory");

    const uint32_t peer = rank ^ 1u;
    uint32_t r_key, r_mbar;
    asm("mapa.shared::cluster.u32 %0, %1, %2;" : "=r"(r_key) : "r"(keybase), "r"(peer));
    asm("mapa.shared::cluster.u32 %0, %1, %2;" : "=r"(r_mbar) : "r"(mbar), "r"(peer));

    float lx = X[0], ly = X[1], lz = X[2];  // first centroid = point 0
    if (rank == 0 && t == 0) {
        float* o = out_xyz + (size_t)b * MM * 3;
        o[0] = lx; o[1] = ly; o[2] = lz;
    }

    for (int s = 1; s < MM; s++) {
        if (t == 0) MBAR_EXPECT_TX(mbar, 128u);  // credits current phase (s-1)

        const ull nlx = f2pack(-lx, -lx);
        const ull nly = f2pack(-ly, -ly);
        const ull nlz = f2pack(-lz, -lz);
        float nd[8];
#pragma unroll
        for (int p = 0; p < 4; p++) {
            ull dx = add2(px2[p], nlx);  // x + (-c) == x - c exactly
            ull dy = add2(py2[p], nly);
            ull dz = add2(pz2[p], nlz);
            ull xx = mul2(dx, dx);
            ull yy = mul2(dy, dy);
            ull zz = mul2(dz, dz);
            ull ss = add2(add2(xx, yy), zz);  // ((dx²+dy²)+dz²)
            float s0, s1;
            f2unpack(s0, s1, ss);
            nd[2 * p] = fminf(dd[2 * p], s0);
            dd[2 * p] = nd[2 * p];
            nd[2 * p + 1] = fminf(dd[2 * p + 1], s1);
            dd[2 * p + 1] = nd[2 * p + 1];
        }
        // thread-local max via FMNMX tree (latency ~12, no predicate chain)
        float bestd = fmaxf(fmaxf(fmaxf(nd[0], nd[1]), fmaxf(nd[2], nd[3])),
                            fmaxf(fmaxf(nd[4], nd[5]), fmaxf(nd[6], nd[7])));
        // warp max (dists >= 0 -> uint order == float order)
        unsigned mx = __reduce_max_sync(0xffffffffu, __float_as_uint(bestd));
        // lowest index matching mx: parallel equality-match + IMNMX tree
        unsigned c[8];
#pragma unroll
        for (int p = 0; p < 4; p++) {
            c[2 * p] = (__float_as_uint(nd[2 * p]) == mx)
                           ? (unsigned)(base + t + (p << 10)) : 0xffffffffu;
            c[2 * p + 1] = (__float_as_uint(nd[2 * p + 1]) == mx)
                               ? (unsigned)(base + t + (p << 10) + 512) : 0xffffffffu;
        }
        unsigned cb = min(min(min(c[0], c[1]), min(c[2], c[3])),
                          min(min(c[4], c[5]), min(c[6], c[7])));
        unsigned wsel = __reduce_min_sync(0xffffffffu, cb);

        if (lane == 0) {
            ull key = ((ull)mx << 32) | wsel;
            keyu[s & 1][warp] = key;  // local slot
            uint32_t dst = r_key + (((s & 1) << 5) + 16 + warp) * 8;  // peer slot
            asm volatile(
                "st.async.shared::cluster.mbarrier::complete_tx::bytes.b64 [%0], %1, [%2];"
                :: "r"(dst), "l"(key), "r"(r_mbar) : "memory");
        }
        __syncthreads();                          // local 16 keys visible
        MBAR_WAIT_PARITY_CLU(mbar, (s - 1) & 1);  // remote 16 keys arrived

        ull k2 = keyu[s & 1][lane];
        unsigned d2 = (unsigned)(k2 >> 32);
        unsigned i2 = (unsigned)k2;
        unsigned mx2 = __reduce_max_sync(0xffffffffu, d2);
        unsigned cand2 = (d2 == mx2) ? i2 : 0xffffffffu;
        int sel = (int)__reduce_min_sync(0xffffffffu, cand2);

        lx = __ldg(X + sel * 3 + 0);
        ly = __ldg(X + sel * 3 + 1);
        lz = __ldg(X + sel * 3 + 2);
        if (rank == 0 && t == 0) {
            float* o = out_xyz + ((size_t)b * MM + s) * 3;
            o[0] = lx; o[1] = ly; o[2] = lz;
        }
    }
}

// ---------------------------------------------------------------------------
// Kernel 2: ball query — one warp per query point, first-32 hits in index
// order, padded with the first hit.
// ---------------------------------------------------------------------------
__global__ __launch_bounds__(256) void ballq_kernel(const float* __restrict__ xyz,
                                                    const float* __restrict__ new_xyz) {
    const int w = (blockIdx.x * blockDim.x + threadIdx.x) >> 5;
    const int lane = threadIdx.x & 31;
    if (w >= BB * MM) return;
    const int b = w >> 10;
    const float* X = xyz + (size_t)b * NN * 3;
    const float cx = new_xyz[w * 3 + 0];
    const float cy = new_xyz[w * 3 + 1];
    const float cz = new_xyz[w * 3 + 2];
    const float R2 = (float)(0.4 * 0.4);  // NOT 0.4f*0.4f (one ulp apart)

    int cnt = 0;
    int first = -1;
    int* out = g_gidx + (size_t)w * KK;

    for (int base = 0; base < NN && cnt < KK; base += 32) {
        int i = base + lane;
        float x = X[i * 3 + 0], y = X[i * 3 + 1], z = X[i * 3 + 2];
        float dx = __fadd_rn(x, -cx);
        float dy = __fadd_rn(y, -cy);
        float dz = __fadd_rn(z, -cz);
        float d2 = __fadd_rn(__fadd_rn(__fmul_rn(dx, dx), __fmul_rn(dy, dy)),
                             __fmul_rn(dz, dz));
        bool hit = d2 < R2;
        unsigned msk = __ballot_sync(0xffffffffu, hit);
        if (msk) {
            if (first < 0) first = base + __ffs(msk) - 1;
            int pos = cnt + __popc(msk & ((1u << lane) - 1u));
            if (hit && pos < KK) out[pos] = i;
            cnt += __popc(msk);
        }
    }
    if (cnt < KK) {
        for (int s2 = cnt + lane; s2 < KK; s2 += 32) out[s2] = first;
    }
}

// ---------------------------------------------------------------------------
// Kernel 3: PERSISTENT fused gather + MLP + maxpool. Grid = 128 blocks
// (1/SM, single wave); each block loads the transposed weights ONCE
// (conflict-free STS: lanes walk the o dimension; the one-time LDG is
// uncoalesced but L2-cached), then loops 8 iterations of 8 groups.
// 2 warps per group split the output dim; per-group named barriers.
// ---------------------------------------------------------------------------
__global__ __launch_bounds__(512) void mlp_kernel(
    const float* __restrict__ xyz, const float* __restrict__ feat,
    const float* __restrict__ w1, const float* __restrict__ b1,
    const float* __restrict__ w2, const float* __restrict__ b2,
    const float* __restrict__ w3, const float* __restrict__ b3,
    const float* __restrict__ new_xyz, float* __restrict__ out_feat) {
    extern __shared__ float sm[];
    float* w1t = sm;            // [67][64]
    float* w2t = sm + 4288;     // [64][64]
    float* w3t = sm + 8384;     // [64][128]
    float* b1s = sm + 16576;
    float* b2s = sm + 16640;
    float* b3s = sm + 16704;
    const int tid = threadIdx.x;
    const int lane = tid & 31;
    const int grp = tid >> 6;        // 8 groups
    const int w2id = (tid >> 5) & 1; // warp within group: o-half
    const int gt = tid & 63;         // thread within group
    float* xs = sm + 16832 + grp * 4192;  // [67][32], reused as h2 [64][32]
    float* h1 = xs + 2144;                // [64][32]

    // ONE-TIME transposed weight load. STS conflict-free: consecutive lanes
    // write consecutive o at fixed c. LDG side is strided (L2-cached).
    for (int e = tid; e < NH1 * CIN; e += 512) {
        int o = e & 63, c = e >> 6;           // c in 0..66
        w1t[c * 64 + o] = __ldg(&w1[o * CIN + c]);
    }
    for (int e = tid; e < NH2 * NH1; e += 512) {
        int o = e & 63, c = e >> 6;
        w2t[c * 64 + o] = __ldg(&w2[o * 64 + c]);
    }
    for (int e = tid; e < NH3 * NH2; e += 512) {
        int o = e & 127, c = e >> 7;
        w3t[c * 128 + o] = __ldg(&w3[o * 64 + c]);
    }
    if (tid < 64) b1s[tid] = b1[tid];
    else if (tid < 128) b2s[tid - 64] = b2[tid - 64];
    else if (tid < 256) b3s[tid - 128] = b3[tid - 128];
    __syncthreads();

    const int barid = grp + 1;
    const int kt = lane & 3;           // 4 k-tiles of 8
    const int ot = lane >> 2;          // 8 o-tiles
    const int ob = w2id * 32 + ot * 4; // layers 1/2: 4 outputs per lane
    const int ob3 = w2id * 64 + ot * 8;

    for (int it = 0; it < 8; it++) {
        const int g = blockIdx.x * 8 + grp + it * 1024;
        const int b = g >> 10;
        const int m = g & 1023;
        const float* Xb = xyz + (size_t)b * NN * 3;
        const float* Fb = feat + (size_t)b * NN * 64;

        // prior iteration's layer-3 xs reads complete before regather
        asm volatile("bar.sync %0, 64;" :: "r"(barid) : "memory");

        // gather [c][k]: half 0 -> rel-xyz + feats 0..31, half 1 -> feats 32..63
        {
            const int k = gt & 31;
            const int fh = gt >> 5;
            const int gi = g_gidx[(size_t)g * KK + k];
            if (fh == 0) {
                xs[0 * 32 + k] = Xb[gi * 3 + 0] - new_xyz[g * 3 + 0];
                xs[1 * 32 + k] = Xb[gi * 3 + 1] - new_xyz[g * 3 + 1];
                xs[2 * 32 + k] = Xb[gi * 3 + 2] - new_xyz[g * 3 + 2];
            }
            const float4* fr = (const float4*)(Fb + (size_t)gi * 64 + fh * 32);
#pragma unroll
            for (int q = 0; q < 8; q++) {
                float4 v = fr[q];
                int c = 3 + fh * 32 + 4 * q;
                xs[(c + 0) * 32 + k] = v.x;
                xs[(c + 1) * 32 + k] = v.y;
                xs[(c + 2) * 32 + k] = v.z;
                xs[(c + 3) * 32 + k] = v.w;
            }
        }
        asm volatile("bar.sync %0, 64;" :: "r"(barid) : "memory");

        // ---- layer 1: 67 -> 64 (this warp: 32 of 64 outputs) ----
        {
            ull acc[4][4];
#pragma unroll
            for (int j = 0; j < 4; j++) {
                float bb = b1s[ob + j];
                ull bp = f2pack(bb, bb);
#pragma unroll
                for (int p = 0; p < 4; p++) acc[j][p] = bp;
            }
            for (int c = 0; c < CIN; c++) {
                ulonglong2 xA = *(const ulonglong2*)&xs[c * 32 + kt * 8];
                ulonglong2 xB = *(const ulonglong2*)&xs[c * 32 + kt * 8 + 4];
                ull xp[4] = {xA.x, xA.y, xB.x, xB.y};
                float4 wv = *(const float4*)&w1t[c * 64 + ob];
                float wf[4] = {wv.x, wv.y, wv.z, wv.w};
#pragma unroll
                for (int j = 0; j < 4; j++) {
                    ull wd = f2pack(wf[j], wf[j]);
#pragma unroll
                    for (int p = 0; p < 4; p++) acc[j][p] = fma2(xp[p], wd, acc[j][p]);
                }
            }
#pragma unroll
            for (int j = 0; j < 4; j++) {
                float r[8];
#pragma unroll
                for (int p = 0; p < 4; p++) f2unpack(r[2 * p], r[2 * p + 1], acc[j][p]);
                float4 v0 = make_float4(fmaxf(r[0], 0.f), fmaxf(r[1], 0.f), fmaxf(r[2], 0.f), fmaxf(r[3], 0.f));
                float4 v1 = make_float4(fmaxf(r[4], 0.f), fmaxf(r[5], 0.f), fmaxf(r[6], 0.f), fmaxf(r[7], 0.f));
                *(float4*)&h1[(ob + j) * 32 + kt * 8] = v0;
                *(float4*)&h1[(ob + j) * 32 + kt * 8 + 4] = v1;
            }
        }
        asm volatile("bar.sync %0, 64;" :: "r"(barid) : "memory");

        // ---- layer 2: 64 -> 64 (reads h1, writes h2 into xs) ----
        {
            ull acc[4][4];
#pragma unroll
            for (int j = 0; j < 4; j++) {
                float bb = b2s[ob + j];
                ull bp = f2pack(bb, bb);
#pragma unroll
                for (int p = 0; p < 4; p++) acc[j][p] = bp;
            }
            for (int c = 0; c < NH1; c++) {
                ulonglong2 xA = *(const ulonglong2*)&h1[c * 32 + kt * 8];
                ulonglong2 xB = *(const ulonglong2*)&h1[c * 32 + kt * 8 + 4];
                ull xp[4] = {xA.x, xA.y, xB.x, xB.y};
                float4 wv = *(const float4*)&w2t[c * 64 + ob];
                float wf[4] = {wv.x, wv.y, wv.z, wv.w};
#pragma unroll
                for (int j = 0; j < 4; j++) {
                    ull wd = f2pack(wf[j], wf[j]);
#pragma unroll
                    for (int p = 0; p < 4; p++) acc[j][p] = fma2(xp[p], wd, acc[j][p]);
                }
            }
#pragma unroll
            for (int j = 0; j < 4; j++) {
                float r[8];
#pragma unroll
                for (int p = 0; p < 4; p++) f2unpack(r[2 * p], r[2 * p + 1], acc[j][p]);
                float4 v0 = make_float4(fmaxf(r[0], 0.f), fmaxf(r[1], 0.f), fmaxf(r[2], 0.f), fmaxf(r[3], 0.f));
                float4 v1 = make_float4(fmaxf(r[4], 0.f), fmaxf(r[5], 0.f), fmaxf(r[6], 0.f), fmaxf(r[7], 0.f));
                *(float4*)&xs[(ob + j) * 32 + kt * 8] = v0;
                *(float4*)&xs[(ob + j) * 32 + kt * 8 + 4] = v1;
            }
        }
        asm volatile("bar.sync %0, 64;" :: "r"(barid) : "memory");

        // ---- layer 3: 64 -> 128 (this warp: 64 outputs), maxpool over k ----
        {
            ull acc[8][4];
#pragma unroll
            for (int j = 0; j < 8; j++) {
                float bb = b3s[ob3 + j];
                ull bp = f2pack(bb, bb);
#pragma unroll
                for (int p = 0; p < 4; p++) acc[j][p] = bp;
            }
            for (int c = 0; c < NH2; c++) {
                ulonglong2 xA = *(const ulonglong2*)&xs[c * 32 + kt * 8];
                ulonglong2 xB = *(const ulonglong2*)&xs[c * 32 + kt * 8 + 4];
                ull xp[4] = {xA.x, xA.y, xB.x, xB.y};
                float4 wA = *(const float4*)&w3t[c * 128 + ob3];
                float4 wB = *(const float4*)&w3t[c * 128 + ob3 + 4];
                float wf[8] = {wA.x, wA.y, wA.z, wA.w, wB.x, wB.y, wB.z, wB.w};
#pragma unroll
                for (int j = 0; j < 8; j++) {
                    ull wd = f2pack(wf[j], wf[j]);
#pragma unroll
                    for (int p = 0; p < 4; p++) acc[j][p] = fma2(xp[p], wd, acc[j][p]);
                }
            }
            float v[8];
#pragma unroll
            for (int j = 0; j < 8; j++) {
                float r[8];
#pragma unroll
                for (int p = 0; p < 4; p++) f2unpack(r[2 * p], r[2 * p + 1], acc[j][p]);
                float mx = fmaxf(fmaxf(fmaxf(r[0], r[1]), fmaxf(r[2], r[3])),
                                 fmaxf(fmaxf(r[4], r[5]), fmaxf(r[6], r[7])));
                v[j] = fmaxf(mx, 0.0f);  // relu commutes with max
            }
#pragma unroll
            for (int d = 1; d < 4; d <<= 1)
#pragma unroll
                for (int j = 0; j < 8; j++)
                    v[j] = fmaxf(v[j], __shfl_xor_sync(0xffffffffu, v[j], d));
            if (kt == 0) {
#pragma unroll
                for (int j = 0; j < 8; j++)
                    out_feat[((size_t)b * NH3 + ob3 + j) * MM + m] = v[j];
            }
        }
    }
}

// ---------------------------------------------------------------------------
extern "C" void kernel_launch(void* const* d_in, const int* in_sizes, int n_in,
                              void* d_out, int out_size) {
    const float* xyz = (const float*)d_in[0];
    const float* feat = (const float*)d_in[1];
    const float* w1 = (const float*)d_in[2];
    const float* b1 = (const float*)d_in[3];
    const float* w2 = (const float*)d_in[4];
    const float* b2 = (const float*)d_in[5];
    const float* w3 = (const float*)d_in[6];
    const float* b3 = (const float*)d_in[7];

    float* out = (float*)d_out;
    float* out_xyz = out;                 // (8,1024,3)
    float* out_feat = out + BB * MM * 3;  // (8,128,1024)

    fps_kernel<<<BB * 2, 512>>>(xyz, out_xyz);
    ballq_kernel<<<(BB * MM * 32) / 256, 256>>>(xyz, out_xyz);

    const int smem_bytes = 50368 * 4;  // 201472 B
    cudaFuncSetAttribute(mlp_kernel, cudaFuncAttributeMaxDynamicSharedMemorySize,
                         smem_bytes);
    mlp_kernel<<<128, 512, smem_bytes>>>(xyz, feat, w1, b1, w2, b2, w3, b3,
                                         out_xyz, out_feat);
}